// round 8
// baseline (speedup 1.0000x reference)
#include <cuda_runtime.h>

#define NN 256
#define BB 2
#define NNODE (BB*NN)

#define RSQRT3 0.5773502691896258f
#define INV_FAN 0.1767766952966369f   // 1/sqrt(32)

// partial G: per (node, half) -> [f*4+c], f in [0,33), f==32 = bias feature
__device__ float g_G2[2*NNODE][132];
// P matrix: row = group*512 + node, 1056 K-entries per row
__device__ float g_P[4*NNODE/ BB * BB][1056];   // 2048 x 1056
// pre-transposed weights: [mat(2)][qb(264)][o(16)][ql(4)]
__device__ float g_WT[2*264*16*4];
__device__ float g_dsum[BB];

#define PACK_F32X2(out, lo, hi) \
    asm("mov.b64 %0, {%1, %2};" : "=l"(out) : "f"(lo), "f"(hi))
#define UNPACK_F32X2(lo, hi, in) \
    asm("mov.b64 {%0, %1}, %2;" : "=f"(lo), "=f"(hi) : "l"(in))
#define FMA_F32X2(d, a, b, c) \
    asm("fma.rn.f32x2 %0, %1, %2, %3;" : "=l"(d) : "l"(a), "l"(b), "l"(c))
#define ADD_F32X2(d, a, b) \
    asm("add.rn.f32x2 %0, %1, %2;" : "=l"(d) : "l"(a), "l"(b))

#define CP_ASYNC16(dst_u32, src_ptr) \
    asm volatile("cp.async.ca.shared.global [%0], [%1], 16;" :: "r"(dst_u32), "l"(src_ptr))
#define CP_COMMIT() asm volatile("cp.async.commit_group;" ::: "memory")
#define CP_WAIT1()  asm volatile("cp.async.wait_group 1;" ::: "memory")
#define CP_WAIT0()  asm volatile("cp.async.wait_group 0;" ::: "memory")

// ---------------------------------------------------------------------------
// Kernel A (unchanged from best run): edge reduction, block per (node, half).
// ---------------------------------------------------------------------------
__global__ __launch_bounds__(256, 3) void edge_kernel(
    const float* __restrict__ edge_attr,
    const float* __restrict__ edge_sh,
    const float* __restrict__ mask,
    const float* __restrict__ fc_w1,
    const float* __restrict__ fc_b1)
{
    __shared__ __align__(16) float ea[2][64 * 32];
    __shared__ __align__(16) float sh[128 * 4];
    __shared__ float w1s[32 * 32];
    __shared__ float b1s[32];
    __shared__ float Gp[8][132];

    const int blk  = blockIdx.x;
    const int node = blk >> 1;
    const int half = blk & 1;
    const int b = node >> 8;
    const int n = node & 255;
    const int m0 = half * 128;
    const int t = threadIdx.x;

    const float* ea_g = edge_attr + (size_t)node * NN * 32 + (size_t)m0 * 32;
    const unsigned ea_u = (unsigned)__cvta_generic_to_shared(&ea[0][0]);

    CP_ASYNC16(ea_u + (unsigned)t * 16u, ea_g + t * 4);
    CP_ASYNC16(ea_u + 4096u + (unsigned)t * 16u, ea_g + 1024 + t * 4);
    CP_COMMIT();
    CP_ASYNC16(ea_u + 8192u + (unsigned)t * 16u, ea_g + 2048 + t * 4);
    CP_ASYNC16(ea_u + 12288u + (unsigned)t * 16u, ea_g + 3072 + t * 4);
    CP_COMMIT();

    for (int i = t; i < 1024; i += 256) w1s[i] = fc_w1[i];
    if (t < 32) b1s[t] = fc_b1[t];
    if (t < 128) {
        int m = m0 + t;
        float mf = mask[b * NN + m] * (m != n ? 1.0f : 0.0f);
        float4 s = ((const float4*)(edge_sh + (size_t)node * NN * 4))[m];
        s.x *= mf; s.y *= mf; s.z *= mf; s.w *= mf;
        ((float4*)sh)[t] = s;
    }
    __syncthreads();

    const int f  = t & 31;
    const int mg = t >> 5;

    unsigned long long w1p[16];
    #pragma unroll
    for (int j = 0; j < 16; j++)
        PACK_F32X2(w1p[j], w1s[(2*j) * 32 + f], w1s[(2*j+1) * 32 + f]);
    unsigned long long bias2;
    PACK_F32X2(bias2, b1s[f], 0.0f);

    unsigned long long acc01 = 0ULL, acc23 = 0ULL;
    const ulonglong2* sh2 = (const ulonglong2*)sh;

    #pragma unroll
    for (int ch = 0; ch < 2; ch++) {
        if (ch == 0) { CP_WAIT1(); } else { CP_WAIT0(); }
        __syncthreads();
        const float* buf = ea[ch];
        #pragma unroll
        for (int it = 0; it < 8; it++) {
            int r = mg + it * 8;
            const ulonglong2* row = (const ulonglong2*)(buf + r * 32);
            unsigned long long c0 = bias2, c1 = 0ULL;
            ulonglong2 u0 = row[0];
            ulonglong2 u1 = row[1];
            ulonglong2 u2 = row[2];
            ulonglong2 u3 = row[3];
            FMA_F32X2(c0, u0.x, w1p[0], c0);
            FMA_F32X2(c1, u0.y, w1p[1], c1);
            FMA_F32X2(c0, u1.x, w1p[2], c0);
            FMA_F32X2(c1, u1.y, w1p[3], c1);
            u0 = row[4];
            u1 = row[5];
            FMA_F32X2(c0, u2.x, w1p[4], c0);
            FMA_F32X2(c1, u2.y, w1p[5], c1);
            FMA_F32X2(c0, u3.x, w1p[6], c0);
            FMA_F32X2(c1, u3.y, w1p[7], c1);
            u2 = row[6];
            u3 = row[7];
            FMA_F32X2(c0, u0.x, w1p[8],  c0);
            FMA_F32X2(c1, u0.y, w1p[9],  c1);
            FMA_F32X2(c0, u1.x, w1p[10], c0);
            FMA_F32X2(c1, u1.y, w1p[11], c1);
            FMA_F32X2(c0, u2.x, w1p[12], c0);
            FMA_F32X2(c1, u2.y, w1p[13], c1);
            FMA_F32X2(c0, u3.x, w1p[14], c0);
            FMA_F32X2(c1, u3.y, w1p[15], c1);
            ADD_F32X2(c0, c0, c1);
            float lo, hi;
            UNPACK_F32X2(lo, hi, c0);
            float h = fmaxf(lo + hi, 0.0f);
            unsigned long long h2;
            PACK_F32X2(h2, h, h);
            ulonglong2 s2 = sh2[ch * 64 + r];
            FMA_F32X2(acc01, h2, s2.x, acc01);
            FMA_F32X2(acc23, h2, s2.y, acc23);
        }
    }

    float o0, o1, o2, o3;
    UNPACK_F32X2(o0, o1, acc01);
    UNPACK_F32X2(o2, o3, acc23);
    Gp[mg][f*4+0] = o0;
    Gp[mg][f*4+1] = o1;
    Gp[mg][f*4+2] = o2;
    Gp[mg][f*4+3] = o3;

    if (t < 32) {
        int c = t & 3, mq = t >> 2;
        float s = 0.f;
        #pragma unroll 8
        for (int m = mq; m < 128; m += 8) s += sh[m * 4 + c];
        Gp[mq][128 + c] = s;
    }
    __syncthreads();

    if (t < 132) {
        float s = 0.f;
        #pragma unroll
        for (int g = 0; g < 8; g++) s += Gp[g][t];
        g_G2[blk][t] = s;
    }
}

// ---------------------------------------------------------------------------
// Kernel B: prep. One block per node: build coefficient planes P, plus
// (blocks 0..127) the pre-transposed weight matrix WT, plus dsum.
//   P row (grp, node), q = half*528 + f*16 + i:
//     grp 0 (S):  half0 A  = G[f,0]*s_in[i]; half1 BC = (G[f,1..3]·v_in[i])*RSQRT3
//     grp 1+x(V): half0 Cx = G[f,1+x]*s_in[i]; half1 Dx = G[f,0]*v_in[i,x]
//   WT[mat][qb][o][ql] = W_mat[q=qb*4+ql][o], mat0=[Wss;Wvv], mat1=[Wsv;Wvs]
// ---------------------------------------------------------------------------
__global__ __launch_bounds__(256) void prep_kernel(
    const float* __restrict__ node_attr,
    const float* __restrict__ mask,
    const float* __restrict__ w_lin_in_s,
    const float* __restrict__ w_lin_in_v,
    const float* __restrict__ fc_w2,
    const float* __restrict__ fc_b2)
{
    __shared__ float Gs[132], sinS[16], vinS[48];
    __shared__ float wls[256], wlv[256];
    __shared__ float red[8];

    const int node = blockIdx.x;
    const int t = threadIdx.x;
    const int b = node >> 8;

    wls[t] = w_lin_in_s[t];
    wlv[t] = w_lin_in_v[t];
    if (t < 132) Gs[t] = g_G2[node*2][t] + g_G2[node*2+1][t];

    if ((node & 255) == 0) {
        float mv = mask[b * NN + t];
        #pragma unroll
        for (int o = 16; o; o >>= 1) mv += __shfl_xor_sync(0xFFFFFFFFu, mv, o);
        if ((t & 31) == 0) red[t >> 5] = mv;
    }
    __syncthreads();
    if ((node & 255) == 0 && t == 0) {
        float s = 0.f;
        #pragma unroll
        for (int i = 0; i < 8; i++) s += red[i];
        g_dsum[b] = s - 1.0f;
    }

    // s_in / v_in
    if (t < 64) {
        const float* na = node_attr + (size_t)node * 64;
        if (t < 16) {
            float s = 0.f;
            #pragma unroll
            for (int i = 0; i < 16; i++) s += na[i] * wls[i * 16 + t];
            sinS[t] = s * 0.25f;
        } else {
            int idx = t - 16;
            int o = idx / 3, x = idx % 3;
            float s = 0.f;
            #pragma unroll
            for (int i = 0; i < 16; i++) s += na[16 + i * 3 + x] * wlv[i * 16 + o];
            vinS[o * 3 + x] = s * 0.25f;
        }
    }
    __syncthreads();

    // WT fill (only blocks 0..127; 264 values each; total 33792)
    if (node < 128) {
        #pragma unroll 2
        for (int j = t; j < 264; j += 256) {
            int gidx = node * 264 + j;
            int mat = gidx / 16896;
            int rem = gidx - mat * 16896;
            int qb = rem >> 6;
            int o  = (rem >> 2) & 15;
            int ql = rem & 3;
            int q = qb * 4 + ql;
            int half = (q >= 528) ? 1 : 0;
            int pf = q - half * 528;
            int f = pf >> 4, i = pf & 15;
            int off = (mat == 0) ? (half ? 256 : 0) : (half ? 768 : 512);
            const float* row = (f < 32) ? (fc_w2 + f * 1024) : fc_b2;
            g_WT[gidx] = row[off + i * 16 + o];
        }
    }

    // P fill: 4 groups x 1056
    #pragma unroll
    for (int k = 0; k < 17; k++) {
        int idx = t + k * 256;
        if (idx < 4224) {
            int grp = idx / 1056;
            int q = idx - grp * 1056;
            int half = (q >= 528) ? 1 : 0;
            int pf = q - half * 528;
            int f = pf >> 4, i = pf & 15;
            const float* G4 = Gs + f * 4;
            float val;
            if (grp == 0) {
                val = half ? (G4[1]*vinS[i*3] + G4[2]*vinS[i*3+1] + G4[3]*vinS[i*3+2]) * RSQRT3
                           : G4[0] * sinS[i];
            } else {
                int x = grp - 1;
                val = half ? G4[0] * vinS[i*3 + x] : G4[1 + x] * sinS[i];
            }
            g_P[grp * 512 + node][q] = val;
        }
    }
}

// ---------------------------------------------------------------------------
// Kernel C: GEMM  Y[2048 x 16] = P @ W (W per row-group), 128 blocks x 4 nodes,
// K=1056 streamed in 8 chunks of 132 through 3 smem buffers (cp.async).
// Inline epilogue: scale, output linear, residual.
// ---------------------------------------------------------------------------
// dynamic smem float offsets
#define GOFF_P(bf)  ((bf)*2112)               // 16 rows x 132
#define GOFF_W(bf)  (6336 + (bf)*4224)        // 2 mats x 33qb x 16o x 4ql
#define GOFF_Y      19008                     // 16 x 17
#define GOFF_WOS    19280
#define GOFF_WOV    19536
#define GSMEM_FLOATS 19792
#define GSMEM_BYTES (GSMEM_FLOATS*4)

__device__ __forceinline__ void gemm_issue(unsigned sm_u32, int c, int t, int n0)
{
    int bf = c % 3;
    // P tile: 16 rows x 132 floats = 528 x 16B
    #pragma unroll
    for (int k = 0; k < 3; k++) {
        int u = t + k * 256;
        if (u < 528) {
            int row = u / 33;
            int j = u - row * 33;
            int g = row >> 2, nl = row & 3;
            const float* src = &g_P[g * 512 + n0 + nl][c * 132 + j * 4];
            unsigned dst = sm_u32 + (unsigned)(GOFF_P(bf) + row * 132 + j * 4) * 4u;
            CP_ASYNC16(dst, src);
        }
    }
    // W tiles: 2 mats x 2112 floats = 1056 x 16B (flat copy, layout preserved)
    #pragma unroll
    for (int k = 0; k < 5; k++) {
        int u = t + k * 256;
        if (u < 1056) {
            int m = u / 528;
            int w = u - m * 528;
            const float* src = g_WT + m * 16896 + c * 2112 + w * 4;
            unsigned dst = sm_u32 + (unsigned)(GOFF_W(bf) + m * 2112 + w * 4) * 4u;
            CP_ASYNC16(dst, src);
        }
    }
    CP_COMMIT();
}

__global__ __launch_bounds__(256) void gemm_kernel(
    const float* __restrict__ node_attr,
    const float* __restrict__ w_lin_out_s,
    const float* __restrict__ w_lin_out_v,
    float* __restrict__ out)
{
    extern __shared__ __align__(16) float sm[];
    const int t = threadIdx.x;
    const int n0 = blockIdx.x * 4;
    const unsigned sm_u32 = (unsigned)__cvta_generic_to_shared(sm);

    gemm_issue(sm_u32, 0, t, n0);
    gemm_issue(sm_u32, 1, t, n0);

    sm[GOFF_WOS + t] = w_lin_out_s[t];
    sm[GOFF_WOV + t] = w_lin_out_v[t];

    const int r = t >> 4;       // row 0..15: r = g*4+nl
    const int o = t & 15;
    const int mat = ((r >> 2) == 0) ? 0 : 1;

    float acc0 = 0.f, acc1 = 0.f;
    #pragma unroll
    for (int c = 0; c < 8; c++) {
        if (c < 7) { CP_WAIT1(); } else { CP_WAIT0(); }
        __syncthreads();
        if (c + 2 < 8) gemm_issue(sm_u32, c + 2, t, n0);
        const float* Pr = sm + GOFF_P(c % 3) + r * 132;
        const float* Wb = sm + GOFF_W(c % 3) + mat * 2112 + o * 4;
        #pragma unroll
        for (int qb = 0; qb < 33; qb += 2) {
            float4 p0 = *(const float4*)(Pr + qb * 4);
            float4 w0 = *(const float4*)(Wb + qb * 64);
            acc0 += p0.x * w0.x + p0.y * w0.y + p0.z * w0.z + p0.w * w0.w;
            if (qb + 1 < 33) {
                float4 p1 = *(const float4*)(Pr + qb * 4 + 4);
                float4 w1 = *(const float4*)(Wb + qb * 64 + 64);
                acc1 += p1.x * w1.x + p1.y * w1.y + p1.z * w1.z + p1.w * w1.w;
            }
        }
    }
    sm[GOFF_Y + r * 17 + o] = acc0 + acc1;
    __syncthreads();

    // epilogue: scale, output linear (/4), residual
    {
        int nl = t >> 6, u = t & 63;
        int node = n0 + nl;
        float scale = INV_FAN / g_dsum[node >> 8];
        const float* na = node_attr + (size_t)node * 64;
        const float* Y = sm + GOFF_Y;
        float rres;
        if (u < 16) {
            float s = 0.f;
            #pragma unroll
            for (int oo = 0; oo < 16; oo++)
                s += Y[nl * 17 + oo] * sm[GOFF_WOS + oo * 16 + u];
            rres = s * scale * 0.25f + na[u];
        } else {
            int idx = u - 16;
            int o2 = idx / 3, x = idx % 3;
            float s = 0.f;
            #pragma unroll
            for (int oo = 0; oo < 16; oo++)
                s += Y[((1 + x) * 4 + nl) * 17 + oo] * sm[GOFF_WOV + oo * 16 + o2];
            rres = s * scale * 0.25f + na[u];
        }
        out[(size_t)node * 64 + u] = rres;
    }
}

extern "C" void kernel_launch(void* const* d_in, const int* in_sizes, int n_in,
                              void* d_out, int out_size) {
    const float* node_attr    = (const float*)d_in[0];
    const float* edge_attr    = (const float*)d_in[1];
    const float* edge_sh      = (const float*)d_in[2];
    const float* mask         = (const float*)d_in[3];
    const float* w_lin_in_s   = (const float*)d_in[4];
    const float* w_lin_in_v   = (const float*)d_in[5];
    const float* fc_w1        = (const float*)d_in[6];
    const float* fc_b1        = (const float*)d_in[7];
    const float* fc_w2        = (const float*)d_in[8];
    const float* fc_b2        = (const float*)d_in[9];
    const float* w_lin_out_s  = (const float*)d_in[10];
    const float* w_lin_out_v  = (const float*)d_in[11];
    float* out = (float*)d_out;

    cudaFuncSetAttribute(gemm_kernel,
                         cudaFuncAttributeMaxDynamicSharedMemorySize, GSMEM_BYTES);

    edge_kernel<<<2 * NNODE, 256>>>(edge_attr, edge_sh, mask, fc_w1, fc_b1);
    prep_kernel<<<NNODE, 256>>>(node_attr, mask, w_lin_in_s, w_lin_in_v,
                                fc_w2, fc_b2);
    gemm_kernel<<<NNODE / 4, 256, GSMEM_BYTES>>>(node_attr,
                                w_lin_out_s, w_lin_out_v, out);
}

// round 9
// speedup vs baseline: 1.2064x; 1.2064x over previous
#include <cuda_runtime.h>

#define NN 256
#define BB 2
#define NNODE (BB*NN)

#define RSQRT3 0.5773502691896258f
#define INV_FAN 0.1767766952966369f   // 1/sqrt(32)

// partial G: per (node, half) -> [f*4+c], f in [0,33), f==32 = bias feature
__device__ float g_G2[2*NNODE][132];

// W1 (32x32, [j][f]) followed by b1 (32) in constant memory
__constant__ float c_w1b[1024 + 32];

#define PACK_F32X2(out, lo, hi) \
    asm("mov.b64 %0, {%1, %2};" : "=l"(out) : "f"(lo), "f"(hi))
#define UNPACK_F32X2(lo, hi, in) \
    asm("mov.b64 {%0, %1}, %2;" : "=f"(lo), "=f"(hi) : "l"(in))
#define FMA_F32X2(d, a, b, c) \
    asm("fma.rn.f32x2 %0, %1, %2, %3;" : "=l"(d) : "l"(a), "l"(b), "l"(c))

#define CP_ASYNC16(dst_u32, src_ptr) \
    asm volatile("cp.async.ca.shared.global [%0], [%1], 16;" :: "r"(dst_u32), "l"(src_ptr))
#define CP_COMMIT() asm volatile("cp.async.commit_group;" ::: "memory")
#define CP_WAIT2()  asm volatile("cp.async.wait_group 2;" ::: "memory")
#define CP_WAIT1()  asm volatile("cp.async.wait_group 1;" ::: "memory")
#define CP_WAIT0()  asm volatile("cp.async.wait_group 0;" ::: "memory")

#define H_PITCH 36

// ---------------------------------------------------------------------------
// Pass-1 worker: one lane owns one ea row (32 floats in regs) and computes
// h[row, F0..F0+15], f32x2-packed over f, weights streamed from constant
// memory (uniform port). Stores relu'd h to smem.
// ---------------------------------------------------------------------------
template<int F0>
__device__ __forceinline__ void h_compute(const float* __restrict__ rr,
                                          float* __restrict__ dst)
{
    unsigned long long acc[8];
    #pragma unroll
    for (int fp = 0; fp < 8; fp++) {
        acc[fp] = *(const unsigned long long*)(c_w1b + 1024 + F0 + fp * 2);
    }
    #pragma unroll
    for (int j = 0; j < 32; j++) {
        float aj = rr[j];
        unsigned long long a2;
        PACK_F32X2(a2, aj, aj);
        #pragma unroll
        for (int fp = 0; fp < 8; fp++) {
            unsigned long long w2 =
                *(const unsigned long long*)(c_w1b + j * 32 + F0 + fp * 2);
            FMA_F32X2(acc[fp], a2, w2, acc[fp]);
        }
    }
    #pragma unroll
    for (int q = 0; q < 4; q++) {
        float a, b, c, d;
        UNPACK_F32X2(a, b, acc[2*q]);
        UNPACK_F32X2(c, d, acc[2*q + 1]);
        float4 st = make_float4(fmaxf(a, 0.f), fmaxf(b, 0.f),
                                fmaxf(c, 0.f), fmaxf(d, 0.f));
        *(float4*)(dst + F0 + q * 4) = st;
    }
}

// ---------------------------------------------------------------------------
// Kernel A: edge reduction, one block per (node, half): 128 m-rows per block.
// Pass 1: h[m,f] = relu(ea[m,:] @ W1[:,f] + b1[f])  (lane = row, W from const)
// Pass 2: Gpart[f,c] = sum_m h[m,f] * sh'[m,c]      (lane = f)
// Gpart[32,c] = sum_m sh'[m,c]                      (bias feature)
// ---------------------------------------------------------------------------
__global__ __launch_bounds__(256, 4) void edge_kernel(
    const float* __restrict__ edge_attr,
    const float* __restrict__ edge_sh,
    const float* __restrict__ mask)
{
    __shared__ __align__(16) float h_s[128 * H_PITCH];   // 18.4 KB
    __shared__ __align__(16) float shp[128 * 4];         // premultiplied sh
    __shared__ float Gp[8][132];

    const int blk  = blockIdx.x;
    const int node = blk >> 1;
    const int half = blk & 1;
    const int b = node >> 8;
    const int n = node & 255;
    const int m0 = half * 128;
    const int t = threadIdx.x;
    const int wid = t >> 5;
    const int lane = t & 31;

    // stage sh' (premultiplied by mask * (m != n))
    if (t < 128) {
        int m = m0 + t;
        float mf = mask[b * NN + m] * (m != n ? 1.0f : 0.0f);
        float4 s = ((const float4*)(edge_sh + (size_t)node * NN * 4))[m];
        s.x *= mf; s.y *= mf; s.z *= mf; s.w *= mf;
        ((float4*)shp)[t] = s;
    }

    // --- pass 1: each lane owns one row; warp pairs split the f range ---
    const int g = wid >> 1;               // row group 0..3
    const int row_l = g * 32 + lane;      // 0..127
    float rr[32];
    {
        const float4* rp = (const float4*)(edge_attr
                            + (size_t)node * NN * 32 + (size_t)(m0 + row_l) * 32);
        #pragma unroll
        for (int k = 0; k < 8; k++) {
            float4 v = rp[k];
            rr[4*k+0] = v.x; rr[4*k+1] = v.y; rr[4*k+2] = v.z; rr[4*k+3] = v.w;
        }
    }
    if ((wid & 1) == 0) h_compute<0>(rr, h_s + row_l * H_PITCH);
    else                h_compute<16>(rr, h_s + row_l * H_PITCH);
    __syncthreads();

    // --- pass 2: lane = f; each warp reduces 16 rows ---
    unsigned long long acc01 = 0ULL, acc23 = 0ULL;
    const ulonglong2* shp2 = (const ulonglong2*)shp;
    #pragma unroll
    for (int it = 0; it < 16; it++) {
        int m = wid * 16 + it;
        float hv = h_s[m * H_PITCH + lane];
        unsigned long long h2;
        PACK_F32X2(h2, hv, hv);
        ulonglong2 s2 = shp2[m];
        FMA_F32X2(acc01, h2, s2.x, acc01);
        FMA_F32X2(acc23, h2, s2.y, acc23);
    }
    {
        float o0, o1, o2, o3;
        UNPACK_F32X2(o0, o1, acc01);
        UNPACK_F32X2(o2, o3, acc23);
        Gp[wid][lane*4+0] = o0;
        Gp[wid][lane*4+1] = o1;
        Gp[wid][lane*4+2] = o2;
        Gp[wid][lane*4+3] = o3;
    }

    // bias feature: G[32][c] = sum_m sh'[m][c]
    if (t < 32) {
        int c = t & 3, mq = t >> 2;
        float s = 0.f;
        #pragma unroll 8
        for (int m = mq; m < 128; m += 8) s += shp[m * 4 + c];
        Gp[mq][128 + c] = s;
    }
    __syncthreads();

    if (t < 132) {
        float s = 0.f;
        #pragma unroll
        for (int g2 = 0; g2 < 8; g2++) s += Gp[g2][t];
        g_G2[blk][t] = s;
    }
}

// ---------------------------------------------------------------------------
// Kernel B (verbatim R6 best): per-node epilogue, 2 nodes/block, 256 blocks.
// W2' streamed in 9 chunks through 4 smem buffers; o-dim packed f32x2;
// partials overlay the stage region.
// ---------------------------------------------------------------------------
#define OFF_STAGE   0
#define OFF_GS      16384
#define OFF_SIN     (OFF_GS + 264)
#define OFF_VIN     (OFF_SIN + 32)
#define OFF_WLS     (OFF_VIN + 96)
#define OFF_WLV     (OFF_WLS + 256)
#define OFF_WOS     (OFF_WLV + 256)
#define OFF_WOV     (OFF_WOS + 256)
#define OFF_OUTS    (OFF_WOV + 256)
#define OFF_OUTV    (OFF_OUTS + 32)
#define OFF_RED     (OFF_OUTV + 96)
#define OFF_DSUM    (OFF_RED + 8)
#define SMEM_FLOATS (OFF_DSUM + 1)
#define SMEM_BYTES  (SMEM_FLOATS * 4)

__device__ __forceinline__ void chunk_compute_p(
    const float* __restrict__ stage_buf, int nrows,
    const float* __restrict__ Gs, int fbase,
    const float* si, const float* x0a, const float* x1a, const float* x2a,
    unsigned long long accS[2][2], unsigned long long accV[2][6],
    int oq, int g)
{
    int f_local = g >> 4;
    int i = g & 15;
    if (f_local >= nrows) return;
    const ulonglong2* W = (const ulonglong2*)(stage_buf + f_local * 1024 + i * 16 + oq * 4);
    ulonglong2 wss = W[0];
    ulonglong2 wvv = W[64];
    ulonglong2 wsv = W[128];
    ulonglong2 wvs = W[192];
    #pragma unroll
    for (int nl = 0; nl < 2; nl++) {
        float4 gv = *(const float4*)(Gs + nl * 132 + (fbase + f_local) * 4);
        float s  = si[nl];
        float x0 = x0a[nl], x1 = x1a[nl], x2 = x2a[nl];
        float a  = gv.x * s;
        float bc = (gv.y * x0 + gv.z * x1 + gv.w * x2) * RSQRT3;
        float c0 = gv.y * s, c1 = gv.z * s, c2 = gv.w * s;
        float d0 = gv.x * x0, d1 = gv.x * x1, d2 = gv.x * x2;
        unsigned long long a2, bc2, c02, c12, c22, d02, d12, d22;
        PACK_F32X2(a2, a, a);     PACK_F32X2(bc2, bc, bc);
        PACK_F32X2(c02, c0, c0);  PACK_F32X2(c12, c1, c1);  PACK_F32X2(c22, c2, c2);
        PACK_F32X2(d02, d0, d0);  PACK_F32X2(d12, d1, d1);  PACK_F32X2(d22, d2, d2);
        FMA_F32X2(accS[nl][0], a2,  wss.x, accS[nl][0]);
        FMA_F32X2(accS[nl][1], a2,  wss.y, accS[nl][1]);
        FMA_F32X2(accS[nl][0], bc2, wvv.x, accS[nl][0]);
        FMA_F32X2(accS[nl][1], bc2, wvv.y, accS[nl][1]);
        FMA_F32X2(accV[nl][0], c02, wsv.x, accV[nl][0]);
        FMA_F32X2(accV[nl][1], c02, wsv.y, accV[nl][1]);
        FMA_F32X2(accV[nl][0], d02, wvs.x, accV[nl][0]);
        FMA_F32X2(accV[nl][1], d02, wvs.y, accV[nl][1]);
        FMA_F32X2(accV[nl][2], c12, wsv.x, accV[nl][2]);
        FMA_F32X2(accV[nl][3], c12, wsv.y, accV[nl][3]);
        FMA_F32X2(accV[nl][2], d12, wvs.x, accV[nl][2]);
        FMA_F32X2(accV[nl][3], d12, wvs.y, accV[nl][3]);
        FMA_F32X2(accV[nl][4], c22, wsv.x, accV[nl][4]);
        FMA_F32X2(accV[nl][5], c22, wsv.y, accV[nl][5]);
        FMA_F32X2(accV[nl][4], d22, wvs.x, accV[nl][4]);
        FMA_F32X2(accV[nl][5], d22, wvs.y, accV[nl][5]);
    }
}

__device__ __forceinline__ void issue_chunk(
    unsigned stage_u32, int nc, int t,
    const float* __restrict__ fc_w2, const float* __restrict__ fc_b2)
{
    unsigned dst = stage_u32 + (unsigned)(nc & 3) * 16384u + (unsigned)t * 16u;
    if (nc < 8) {
        const float* src = fc_w2 + nc * 4096 + t * 4;
        #pragma unroll
        for (int r = 0; r < 4; r++)
            CP_ASYNC16(dst + r * 4096u, src + r * 1024);
    } else {
        CP_ASYNC16(dst, fc_b2 + t * 4);
    }
    CP_COMMIT();
}

__global__ __launch_bounds__(256, 3) void node_kernel(
    const float* __restrict__ node_attr,
    const float* __restrict__ mask,
    const float* __restrict__ w_lin_in_s,
    const float* __restrict__ w_lin_in_v,
    const float* __restrict__ fc_w2,
    const float* __restrict__ fc_b2,
    const float* __restrict__ w_lin_out_s,
    const float* __restrict__ w_lin_out_v,
    float* __restrict__ out)
{
    extern __shared__ __align__(16) float sm[];
    float* stage = sm + OFF_STAGE;
    float* part  = sm + OFF_STAGE;
    float* Gs    = sm + OFF_GS;
    float* sinS  = sm + OFF_SIN;
    float* vinS  = sm + OFF_VIN;
    float* wls   = sm + OFF_WLS;
    float* wlv   = sm + OFF_WLV;
    float* wos   = sm + OFF_WOS;
    float* wov   = sm + OFF_WOV;
    float* outsS = sm + OFF_OUTS;
    float* outvS = sm + OFF_OUTV;
    float* red   = sm + OFF_RED;

    const int t = threadIdx.x;
    const int node0 = blockIdx.x * 2;
    const int b = node0 >> 8;

    const unsigned stage_u32 = (unsigned)__cvta_generic_to_shared(stage);

    issue_chunk(stage_u32, 0, t, fc_w2, fc_b2);
    issue_chunk(stage_u32, 1, t, fc_w2, fc_b2);
    issue_chunk(stage_u32, 2, t, fc_w2, fc_b2);

    wls[t] = w_lin_in_s[t];
    wlv[t] = w_lin_in_v[t];
    wos[t] = w_lin_out_s[t];
    wov[t] = w_lin_out_v[t];
    if (t < 132) {
        #pragma unroll
        for (int nl = 0; nl < 2; nl++)
            Gs[nl*132 + t] = g_G2[(node0 + nl)*2][t] + g_G2[(node0 + nl)*2 + 1][t];
    }
    {
        float mv = mask[b * NN + t];
        #pragma unroll
        for (int o = 16; o; o >>= 1) mv += __shfl_xor_sync(0xFFFFFFFFu, mv, o);
        if ((t & 31) == 0) red[t >> 5] = mv;
    }
    __syncthreads();
    if (t == 0) {
        float s = 0.f;
        #pragma unroll
        for (int i = 0; i < 8; i++) s += red[i];
        sm[OFF_DSUM] = s - 1.0f;
    }

    if (t < 128) {
        int nl = t >> 6, u = t & 63;
        const float* na = node_attr + (size_t)(node0 + nl) * 64;
        if (u < 16) {
            float s = 0.f;
            #pragma unroll
            for (int i = 0; i < 16; i++) s += na[i] * wls[i * 16 + u];
            sinS[nl*16 + u] = s * 0.25f;
        } else {
            int idx = u - 16;
            int o = idx / 3, x = idx % 3;
            float s = 0.f;
            #pragma unroll
            for (int i = 0; i < 16; i++) s += na[16 + i * 3 + x] * wlv[i * 16 + o];
            vinS[nl*48 + o * 3 + x] = s * 0.25f;
        }
    }
    __syncthreads();

    const int oq = t & 3;
    const int g  = t >> 2;

    float si[2], x0a[2], x1a[2], x2a[2];
    {
        int i = g & 15;
        #pragma unroll
        for (int nl = 0; nl < 2; nl++) {
            si[nl]  = sinS[nl*16 + i];
            x0a[nl] = vinS[nl*48 + i*3 + 0];
            x1a[nl] = vinS[nl*48 + i*3 + 1];
            x2a[nl] = vinS[nl*48 + i*3 + 2];
        }
    }

    unsigned long long accS[2][2];
    unsigned long long accV[2][6];
    #pragma unroll
    for (int nl = 0; nl < 2; nl++) {
        accS[nl][0] = accS[nl][1] = 0ULL;
        #pragma unroll
        for (int q = 0; q < 6; q++) accV[nl][q] = 0ULL;
    }

    #pragma unroll
    for (int c = 0; c < 9; c++) {
        if (c < 7) { CP_WAIT2(); } else if (c == 7) { CP_WAIT1(); } else { CP_WAIT0(); }
        __syncthreads();
        if (c + 3 <= 8) issue_chunk(stage_u32, c + 3, t, fc_w2, fc_b2);
        chunk_compute_p(stage + (c & 3) * 4096, (c < 8) ? 4 : 1, Gs, c * 4,
                        si, x0a, x1a, x2a, accS, accV, oq, g);
    }

    __syncthreads();

    #pragma unroll
    for (int nl = 0; nl < 2; nl++) {
        #pragma unroll
        for (int h = 0; h < 2; h++) {
            float v0, v1;
            UNPACK_F32X2(v0, v1, accS[nl][h]);
            part[(nl*16 + oq*4 + h*2 + 0) * 68 + g] = v0;
            part[(nl*16 + oq*4 + h*2 + 1) * 68 + g] = v1;
        }
        #pragma unroll
        for (int x = 0; x < 3; x++)
            #pragma unroll
            for (int h = 0; h < 2; h++) {
                float v0, v1;
                UNPACK_F32X2(v0, v1, accV[nl][x*2 + h]);
                int o = oq*4 + h*2;
                part[(32 + nl*48 + o*3 + x) * 68 + g] = v0;
                part[(32 + nl*48 + (o+1)*3 + x) * 68 + g] = v1;
            }
    }
    __syncthreads();

    if (t < 128) {
        float scale = INV_FAN / sm[OFF_DSUM];
        const float4* row = (const float4*)(part + t * 68);
        float s = 0.f;
        #pragma unroll
        for (int j = 0; j < 16; j++) {
            float4 v = row[j];
            s += (v.x + v.y) + (v.z + v.w);
        }
        if (t < 32) outsS[t] = s * scale;
        else        outvS[t - 32] = s * scale;
    }
    __syncthreads();

    if (t < 128) {
        int nl = t >> 6, u = t & 63;
        const float* na = node_attr + (size_t)(node0 + nl) * 64;
        float r;
        if (u < 16) {
            float s = 0.f;
            #pragma unroll
            for (int o = 0; o < 16; o++) s += outsS[nl*16 + o] * wos[o * 16 + u];
            r = s * 0.25f + na[u];
        } else {
            int idx = u - 16;
            int o2 = idx / 3, x = idx % 3;
            float s = 0.f;
            #pragma unroll
            for (int o = 0; o < 16; o++) s += outvS[nl*48 + o * 3 + x] * wov[o * 16 + o2];
            r = s * 0.25f + na[u];
        }
        out[(size_t)(node0 + nl) * 64 + u] = r;
    }
}

extern "C" void kernel_launch(void* const* d_in, const int* in_sizes, int n_in,
                              void* d_out, int out_size) {
    const float* node_attr    = (const float*)d_in[0];
    const float* edge_attr    = (const float*)d_in[1];
    const float* edge_sh      = (const float*)d_in[2];
    const float* mask         = (const float*)d_in[3];
    const float* w_lin_in_s   = (const float*)d_in[4];
    const float* w_lin_in_v   = (const float*)d_in[5];
    const float* fc_w1        = (const float*)d_in[6];
    const float* fc_b1        = (const float*)d_in[7];
    const float* fc_w2        = (const float*)d_in[8];
    const float* fc_b2        = (const float*)d_in[9];
    const float* w_lin_out_s  = (const float*)d_in[10];
    const float* w_lin_out_v  = (const float*)d_in[11];
    float* out = (float*)d_out;

    cudaFuncSetAttribute(node_kernel,
                         cudaFuncAttributeMaxDynamicSharedMemorySize, SMEM_BYTES);

    // W1 + b1 into constant memory (D2D async memcpys; graph-capturable)
    cudaMemcpyToSymbolAsync(c_w1b, fc_w1, 1024 * sizeof(float), 0,
                            cudaMemcpyDeviceToDevice, 0);
    cudaMemcpyToSymbolAsync(c_w1b, fc_b1, 32 * sizeof(float),
                            1024 * sizeof(float),
                            cudaMemcpyDeviceToDevice, 0);

    edge_kernel<<<2 * NNODE, 256>>>(edge_attr, edge_sh, mask);
    node_kernel<<<NNODE / 2, 256, SMEM_BYTES>>>(node_attr, mask,
                                    w_lin_in_s, w_lin_in_v,
                                    fc_w2, fc_b2, w_lin_out_s, w_lin_out_v, out);
}

// round 11
// speedup vs baseline: 1.2339x; 1.0228x over previous
#include <cuda_runtime.h>

#define NN 256
#define BB 2
#define NNODE (BB*NN)

#define RSQRT3 0.5773502691896258f
#define INV_FAN 0.1767766952966369f   // 1/sqrt(32)

// G[node][f*4+c], f in [0,33), f==32 = bias (constant-1) feature
__device__ float g_G[NNODE][132];

#define PACK_F32X2(out, lo, hi) \
    asm("mov.b64 %0, {%1, %2};" : "=l"(out) : "f"(lo), "f"(hi))
#define UNPACK_F32X2(lo, hi, in) \
    asm("mov.b64 {%0, %1}, %2;" : "=f"(lo), "=f"(hi) : "l"(in))
#define FMA_F32X2(d, a, b, c) \
    asm("fma.rn.f32x2 %0, %1, %2, %3;" : "=l"(d) : "l"(a), "l"(b), "l"(c))

#define CP_ASYNC16(dst_u32, src_ptr) \
    asm volatile("cp.async.ca.shared.global [%0], [%1], 16;" :: "r"(dst_u32), "l"(src_ptr))
#define CP_COMMIT() asm volatile("cp.async.commit_group;" ::: "memory")
#define CP_WAIT3()  asm volatile("cp.async.wait_group 3;" ::: "memory")
#define CP_WAIT2()  asm volatile("cp.async.wait_group 2;" ::: "memory")
#define CP_WAIT1()  asm volatile("cp.async.wait_group 1;" ::: "memory")
#define CP_WAIT0()  asm volatile("cp.async.wait_group 0;" ::: "memory")

#define EA_PITCH 36   // floats per staged row (conflict-free for 2-row stride)

// ---------------------------------------------------------------------------
// Kernel A: edge reduction, one block per node (256 rows, 4 chunks of 64).
// Register-tiled: thread = (2 rows x 4 f). h = relu(ea@W1 + b1);
// G[f,c] = sum_m h[m,f]*sh'[m,c]; G[32,c] = sum_m sh'[m,c].
// ---------------------------------------------------------------------------
__global__ __launch_bounds__(256, 3) void edge_kernel(
    const float* __restrict__ edge_attr,
    const float* __restrict__ edge_sh,
    const float* __restrict__ mask,
    const float* __restrict__ fc_w1,
    const float* __restrict__ fc_b1)
{
    __shared__ __align__(16) float eas[4][64 * EA_PITCH];  // 36.9 KB
    __shared__ __align__(16) float shp[256 * 4];           // premultiplied sh
    __shared__ __align__(16) float w1s[1024];              // [j][f]
    __shared__ float b1s[32];
    __shared__ float Gp[8][132];

    const int node = blockIdx.x;
    const int b = node >> 8;
    const int n = node & 255;
    const int t = threadIdx.x;
    const int lane = t & 31;
    const int wid = t >> 5;
    const int fg = t & 7;      // f group: f = fg*4 + ff
    const int rg = t >> 3;     // row group: rows rg*2, rg*2+1 (within chunk)

    const float* ea_g = edge_attr + (size_t)node * NN * 32;
    const unsigned eas_u = (unsigned)__cvta_generic_to_shared(&eas[0][0]);

    // issue all 4 chunks (64 rows x 128 B each; pitch-36 staging)
    #pragma unroll
    for (int c = 0; c < 4; c++) {
        #pragma unroll
        for (int k = 0; k < 2; k++) {
            int u = t + k * 256;
            int row = u >> 3, seg = u & 7;
            unsigned dst = eas_u + (unsigned)(c * 64 * EA_PITCH + row * EA_PITCH + seg * 4) * 4u;
            CP_ASYNC16(dst, ea_g + (c * 64 + row) * 32 + seg * 4);
        }
        CP_COMMIT();
    }

    // stage W1, b1, premultiplied sh'
    ((float4*)w1s)[t] = ((const float4*)fc_w1)[t];
    if (t < 32) b1s[t] = fc_b1[t];
    {
        float mf = mask[b * NN + t] * (t != n ? 1.0f : 0.0f);
        float4 s = ((const float4*)(edge_sh + (size_t)node * NN * 4))[t];
        s.x *= mf; s.y *= mf; s.z *= mf; s.w *= mf;
        ((float4*)shp)[t] = s;
    }
    __syncthreads();

    unsigned long long b1p0 = *(const unsigned long long*)(b1s + fg * 4);
    unsigned long long b1p1 = *(const unsigned long long*)(b1s + fg * 4 + 2);

    unsigned long long Gacc[8];   // [ff*2 + cpair]
    #pragma unroll
    for (int k = 0; k < 8; k++) Gacc[k] = 0ULL;

    #pragma unroll
    for (int c = 0; c < 4; c++) {
        if (c == 0) { CP_WAIT3(); } else if (c == 1) { CP_WAIT2(); }
        else if (c == 2) { CP_WAIT1(); } else { CP_WAIT0(); }
        __syncthreads();

        const float* row0 = &eas[c][0] + (rg * 2) * EA_PITCH;
        const float* row1 = row0 + EA_PITCH;

        unsigned long long h00 = b1p0, h01 = b1p1;   // row0: f pairs
        unsigned long long h10 = b1p0, h11 = b1p1;   // row1

        #pragma unroll
        for (int jc = 0; jc < 8; jc++) {
            float4 a0 = ((const float4*)row0)[jc];
            float4 a1 = ((const float4*)row1)[jc];
            const float* wb = w1s + (jc * 4) * 32 + fg * 4;
            #pragma unroll
            for (int jj = 0; jj < 4; jj++) {
                unsigned long long w0 = *(const unsigned long long*)(wb + jj * 32);
                unsigned long long w1 = *(const unsigned long long*)(wb + jj * 32 + 2);
                float a0j = (jj == 0) ? a0.x : (jj == 1) ? a0.y : (jj == 2) ? a0.z : a0.w;
                float a1j = (jj == 0) ? a1.x : (jj == 1) ? a1.y : (jj == 2) ? a1.z : a1.w;
                unsigned long long a0d, a1d;
                PACK_F32X2(a0d, a0j, a0j);
                PACK_F32X2(a1d, a1j, a1j);
                FMA_F32X2(h00, a0d, w0, h00);
                FMA_F32X2(h01, a0d, w1, h01);
                FMA_F32X2(h10, a1d, w0, h10);
                FMA_F32X2(h11, a1d, w1, h11);
            }
        }

        // chunk epilogue: relu + multiply by sh', accumulate G
        int gr = c * 64 + rg * 2;
        float4 s0v = ((const float4*)shp)[gr];
        float4 s1v = ((const float4*)shp)[gr + 1];
        #pragma unroll
        for (int rr = 0; rr < 2; rr++) {
            float h0, h1, h2, h3;
            if (rr == 0) { UNPACK_F32X2(h0, h1, h00); UNPACK_F32X2(h2, h3, h01); }
            else         { UNPACK_F32X2(h0, h1, h10); UNPACK_F32X2(h2, h3, h11); }
            h0 = fmaxf(h0, 0.f); h1 = fmaxf(h1, 0.f);
            h2 = fmaxf(h2, 0.f); h3 = fmaxf(h3, 0.f);
            float4 sv = (rr == 0) ? s0v : s1v;
            unsigned long long sp01, sp23, hd;
            PACK_F32X2(sp01, sv.x, sv.y);
            PACK_F32X2(sp23, sv.z, sv.w);
            PACK_F32X2(hd, h0, h0);
            FMA_F32X2(Gacc[0], hd, sp01, Gacc[0]);
            FMA_F32X2(Gacc[1], hd, sp23, Gacc[1]);
            PACK_F32X2(hd, h1, h1);
            FMA_F32X2(Gacc[2], hd, sp01, Gacc[2]);
            FMA_F32X2(Gacc[3], hd, sp23, Gacc[3]);
            PACK_F32X2(hd, h2, h2);
            FMA_F32X2(Gacc[4], hd, sp01, Gacc[4]);
            FMA_F32X2(Gacc[5], hd, sp23, Gacc[5]);
            PACK_F32X2(hd, h3, h3);
            FMA_F32X2(Gacc[6], hd, sp01, Gacc[6]);
            FMA_F32X2(Gacc[7], hd, sp23, Gacc[7]);
        }
        if (c < 3) __syncthreads();   // before next wait/overwrite ordering
    }

    // reduce across row-groups within each warp (lane bits 3,4)
    #pragma unroll
    for (int k = 0; k < 8; k++) {
        float lo, hi, lo2, hi2;
        unsigned long long other = __shfl_xor_sync(0xFFFFFFFFu, Gacc[k], 8);
        UNPACK_F32X2(lo, hi, Gacc[k]); UNPACK_F32X2(lo2, hi2, other);
        PACK_F32X2(Gacc[k], lo + lo2, hi + hi2);
        other = __shfl_xor_sync(0xFFFFFFFFu, Gacc[k], 16);
        UNPACK_F32X2(lo, hi, Gacc[k]); UNPACK_F32X2(lo2, hi2, other);
        PACK_F32X2(Gacc[k], lo + lo2, hi + hi2);
    }
    if (lane < 8) {   // lane == fg; holds warp-partial for f = lane*4+ff
        #pragma unroll
        for (int ff = 0; ff < 4; ff++) {
            float c0, c1, c2, c3;
            UNPACK_F32X2(c0, c1, Gacc[ff * 2 + 0]);
            UNPACK_F32X2(c2, c3, Gacc[ff * 2 + 1]);
            *(float4*)(&Gp[wid][lane * 16 + ff * 4]) = make_float4(c0, c1, c2, c3);
        }
    }

    // bias feature: G[32][c] = sum_m sh'[m][c]
    if (t < 32) {
        int cc = t & 3, mq = t >> 2;
        float s = 0.f;
        #pragma unroll 8
        for (int m = mq; m < 256; m += 8) s += shp[m * 4 + cc];
        Gp[mq][128 + cc] = s;
    }
    __syncthreads();

    if (t < 132) {
        float s = 0.f;
        #pragma unroll
        for (int g2 = 0; g2 < 8; g2++) s += Gp[g2][t];
        g_G[node][t] = s;
    }
}

// ---------------------------------------------------------------------------
// Kernel B (R6 best, unchanged except unified g_G): 2 nodes/block, 256 blocks.
// ---------------------------------------------------------------------------
#define OFF_STAGE   0
#define OFF_GS      16384
#define OFF_SIN     (OFF_GS + 264)
#define OFF_VIN     (OFF_SIN + 32)
#define OFF_WLS     (OFF_VIN + 96)
#define OFF_WLV     (OFF_WLS + 256)
#define OFF_WOS     (OFF_WLV + 256)
#define OFF_WOV     (OFF_WOS + 256)
#define OFF_OUTS    (OFF_WOV + 256)
#define OFF_OUTV    (OFF_OUTS + 32)
#define OFF_RED     (OFF_OUTV + 96)
#define OFF_DSUM    (OFF_RED + 8)
#define SMEM_FLOATS (OFF_DSUM + 1)
#define SMEM_BYTES  (SMEM_FLOATS * 4)

__device__ __forceinline__ void chunk_compute_p(
    const float* __restrict__ stage_buf, int nrows,
    const float* __restrict__ Gs, int fbase,
    const float* si, const float* x0a, const float* x1a, const float* x2a,
    unsigned long long accS[2][2], unsigned long long accV[2][6],
    int oq, int g)
{
    int f_local = g >> 4;
    int i = g & 15;
    if (f_local >= nrows) return;
    const ulonglong2* W = (const ulonglong2*)(stage_buf + f_local * 1024 + i * 16 + oq * 4);
    ulonglong2 wss = W[0];
    ulonglong2 wvv = W[64];
    ulonglong2 wsv = W[128];
    ulonglong2 wvs = W[192];
    #pragma unroll
    for (int nl = 0; nl < 2; nl++) {
        float4 gv = *(const float4*)(Gs + nl * 132 + (fbase + f_local) * 4);
        float s  = si[nl];
        float x0 = x0a[nl], x1 = x1a[nl], x2 = x2a[nl];
        float a  = gv.x * s;
        float bc = (gv.y * x0 + gv.z * x1 + gv.w * x2) * RSQRT3;
        float c0 = gv.y * s, c1 = gv.z * s, c2 = gv.w * s;
        float d0 = gv.x * x0, d1 = gv.x * x1, d2 = gv.x * x2;
        unsigned long long a2, bc2, c02, c12, c22, d02, d12, d22;
        PACK_F32X2(a2, a, a);     PACK_F32X2(bc2, bc, bc);
        PACK_F32X2(c02, c0, c0);  PACK_F32X2(c12, c1, c1);  PACK_F32X2(c22, c2, c2);
        PACK_F32X2(d02, d0, d0);  PACK_F32X2(d12, d1, d1);  PACK_F32X2(d22, d2, d2);
        FMA_F32X2(accS[nl][0], a2,  wss.x, accS[nl][0]);
        FMA_F32X2(accS[nl][1], a2,  wss.y, accS[nl][1]);
        FMA_F32X2(accS[nl][0], bc2, wvv.x, accS[nl][0]);
        FMA_F32X2(accS[nl][1], bc2, wvv.y, accS[nl][1]);
        FMA_F32X2(accV[nl][0], c02, wsv.x, accV[nl][0]);
        FMA_F32X2(accV[nl][1], c02, wsv.y, accV[nl][1]);
        FMA_F32X2(accV[nl][0], d02, wvs.x, accV[nl][0]);
        FMA_F32X2(accV[nl][1], d02, wvs.y, accV[nl][1]);
        FMA_F32X2(accV[nl][2], c12, wsv.x, accV[nl][2]);
        FMA_F32X2(accV[nl][3], c12, wsv.y, accV[nl][3]);
        FMA_F32X2(accV[nl][2], d12, wvs.x, accV[nl][2]);
        FMA_F32X2(accV[nl][3], d12, wvs.y, accV[nl][3]);
        FMA_F32X2(accV[nl][4], c22, wsv.x, accV[nl][4]);
        FMA_F32X2(accV[nl][5], c22, wsv.y, accV[nl][5]);
        FMA_F32X2(accV[nl][4], d22, wvs.x, accV[nl][4]);
        FMA_F32X2(accV[nl][5], d22, wvs.y, accV[nl][5]);
    }
}

__device__ __forceinline__ void issue_chunk(
    unsigned stage_u32, int nc, int t,
    const float* __restrict__ fc_w2, const float* __restrict__ fc_b2)
{
    unsigned dst = stage_u32 + (unsigned)(nc & 3) * 16384u + (unsigned)t * 16u;
    if (nc < 8) {
        const float* src = fc_w2 + nc * 4096 + t * 4;
        #pragma unroll
        for (int r = 0; r < 4; r++)
            CP_ASYNC16(dst + r * 4096u, src + r * 1024);
    } else {
        CP_ASYNC16(dst, fc_b2 + t * 4);
    }
    CP_COMMIT();
}

__global__ __launch_bounds__(256, 3) void node_kernel(
    const float* __restrict__ node_attr,
    const float* __restrict__ mask,
    const float* __restrict__ w_lin_in_s,
    const float* __restrict__ w_lin_in_v,
    const float* __restrict__ fc_w2,
    const float* __restrict__ fc_b2,
    const float* __restrict__ w_lin_out_s,
    const float* __restrict__ w_lin_out_v,
    float* __restrict__ out)
{
    extern __shared__ __align__(16) float sm[];
    float* stage = sm + OFF_STAGE;
    float* part  = sm + OFF_STAGE;
    float* Gs    = sm + OFF_GS;
    float* sinS  = sm + OFF_SIN;
    float* vinS  = sm + OFF_VIN;
    float* wls   = sm + OFF_WLS;
    float* wlv   = sm + OFF_WLV;
    float* wos   = sm + OFF_WOS;
    float* wov   = sm + OFF_WOV;
    float* outsS = sm + OFF_OUTS;
    float* outvS = sm + OFF_OUTV;
    float* red   = sm + OFF_RED;

    const int t = threadIdx.x;
    const int node0 = blockIdx.x * 2;
    const int b = node0 >> 8;

    const unsigned stage_u32 = (unsigned)__cvta_generic_to_shared(stage);

    issue_chunk(stage_u32, 0, t, fc_w2, fc_b2);
    issue_chunk(stage_u32, 1, t, fc_w2, fc_b2);
    issue_chunk(stage_u32, 2, t, fc_w2, fc_b2);

    wls[t] = w_lin_in_s[t];
    wlv[t] = w_lin_in_v[t];
    wos[t] = w_lin_out_s[t];
    wov[t] = w_lin_out_v[t];
    if (t < 132) {
        #pragma unroll
        for (int nl = 0; nl < 2; nl++)
            Gs[nl*132 + t] = g_G[node0 + nl][t];
    }
    {
        float mv = mask[b * NN + t];
        #pragma unroll
        for (int o = 16; o; o >>= 1) mv += __shfl_xor_sync(0xFFFFFFFFu, mv, o);
        if ((t & 31) == 0) red[t >> 5] = mv;
    }
    __syncthreads();
    if (t == 0) {
        float s = 0.f;
        #pragma unroll
        for (int i = 0; i < 8; i++) s += red[i];
        sm[OFF_DSUM] = s - 1.0f;
    }

    if (t < 128) {
        int nl = t >> 6, u = t & 63;
        const float* na = node_attr + (size_t)(node0 + nl) * 64;
        if (u < 16) {
            float s = 0.f;
            #pragma unroll
            for (int i = 0; i < 16; i++) s += na[i] * wls[i * 16 + u];
            sinS[nl*16 + u] = s * 0.25f;
        } else {
            int idx = u - 16;
            int o = idx / 3, x = idx % 3;
            float s = 0.f;
            #pragma unroll
            for (int i = 0; i < 16; i++) s += na[16 + i * 3 + x] * wlv[i * 16 + o];
            vinS[nl*48 + o * 3 + x] = s * 0.25f;
        }
    }
    __syncthreads();

    const int oq = t & 3;
    const int g  = t >> 2;

    float si[2], x0a[2], x1a[2], x2a[2];
    {
        int i = g & 15;
        #pragma unroll
        for (int nl = 0; nl < 2; nl++) {
            si[nl]  = sinS[nl*16 + i];
            x0a[nl] = vinS[nl*48 + i*3 + 0];
            x1a[nl] = vinS[nl*48 + i*3 + 1];
            x2a[nl] = vinS[nl*48 + i*3 + 2];
        }
    }

    unsigned long long accS[2][2];
    unsigned long long accV[2][6];
    #pragma unroll
    for (int nl = 0; nl < 2; nl++) {
        accS[nl][0] = accS[nl][1] = 0ULL;
        #pragma unroll
        for (int q = 0; q < 6; q++) accV[nl][q] = 0ULL;
    }

    #pragma unroll
    for (int c = 0; c < 9; c++) {
        if (c < 7) { CP_WAIT2(); } else if (c == 7) { CP_WAIT1(); } else { CP_WAIT0(); }
        __syncthreads();
        if (c + 3 <= 8) issue_chunk(stage_u32, c + 3, t, fc_w2, fc_b2);
        chunk_compute_p(stage + (c & 3) * 4096, (c < 8) ? 4 : 1, Gs, c * 4,
                        si, x0a, x1a, x2a, accS, accV, oq, g);
    }

    __syncthreads();

    #pragma unroll
    for (int nl = 0; nl < 2; nl++) {
        #pragma unroll
        for (int h = 0; h < 2; h++) {
            float v0, v1;
            UNPACK_F32X2(v0, v1, accS[nl][h]);
            part[(nl*16 + oq*4 + h*2 + 0) * 68 + g] = v0;
            part[(nl*16 + oq*4 + h*2 + 1) * 68 + g] = v1;
        }
        #pragma unroll
        for (int x = 0; x < 3; x++)
            #pragma unroll
            for (int h = 0; h < 2; h++) {
                float v0, v1;
                UNPACK_F32X2(v0, v1, accV[nl][x*2 + h]);
                int o = oq*4 + h*2;
                part[(32 + nl*48 + o*3 + x) * 68 + g] = v0;
                part[(32 + nl*48 + (o+1)*3 + x) * 68 + g] = v1;
            }
    }
    __syncthreads();

    if (t < 128) {
        float scale = INV_FAN / sm[OFF_DSUM];
        const float4* row = (const float4*)(part + t * 68);
        float s = 0.f;
        #pragma unroll
        for (int j = 0; j < 16; j++) {
            float4 v = row[j];
            s += (v.x + v.y) + (v.z + v.w);
        }
        if (t < 32) outsS[t] = s * scale;
        else        outvS[t - 32] = s * scale;
    }
    __syncthreads();

    if (t < 128) {
        int nl = t >> 6, u = t & 63;
        const float* na = node_attr + (size_t)(node0 + nl) * 64;
        float r;
        if (u < 16) {
            float s = 0.f;
            #pragma unroll
            for (int o = 0; o < 16; o++) s += outsS[nl*16 + o] * wos[o * 16 + u];
            r = s * 0.25f + na[u];
        } else {
            int idx = u - 16;
            int o2 = idx / 3, x = idx % 3;
            float s = 0.f;
            #pragma unroll
            for (int o = 0; o < 16; o++) s += outvS[nl*48 + o * 3 + x] * wov[o * 16 + o2];
            r = s * 0.25f + na[u];
        }
        out[(size_t)(node0 + nl) * 64 + u] = r;
    }
}

extern "C" void kernel_launch(void* const* d_in, const int* in_sizes, int n_in,
                              void* d_out, int out_size) {
    const float* node_attr    = (const float*)d_in[0];
    const float* edge_attr    = (const float*)d_in[1];
    const float* edge_sh      = (const float*)d_in[2];
    const float* mask         = (const float*)d_in[3];
    const float* w_lin_in_s   = (const float*)d_in[4];
    const float* w_lin_in_v   = (const float*)d_in[5];
    const float* fc_w1        = (const float*)d_in[6];
    const float* fc_b1        = (const float*)d_in[7];
    const float* fc_w2        = (const float*)d_in[8];
    const float* fc_b2        = (const float*)d_in[9];
    const float* w_lin_out_s  = (const float*)d_in[10];
    const float* w_lin_out_v  = (const float*)d_in[11];
    float* out = (float*)d_out;

    cudaFuncSetAttribute(node_kernel,
                         cudaFuncAttributeMaxDynamicSharedMemorySize, SMEM_BYTES);

    edge_kernel<<<NNODE, 256>>>(edge_attr, edge_sh, mask, fc_w1, fc_b1);
    node_kernel<<<NNODE / 2, 256, SMEM_BYTES>>>(node_attr, mask,
                                    w_lin_in_s, w_lin_in_v,
                                    fc_w2, fc_b2, w_lin_out_s, w_lin_out_v, out);
}